// round 5
// baseline (speedup 1.0000x reference)
#include <cuda_runtime.h>

// 96 fp32 outputs, a = x1.reshape(4,2), b = x2.reshape(4,2):
//   [ 0,16) x3 = a@b.T   [16,32) x4 = x3.T   [32,40) v1 = a
//   [40,48) v2 = a.T     [48,52) v3 = a.T@a  [52,68) v4 = a@a.T
//   [68,72) v5 = b.T@a   [72,88) v6 = x3     [88,96) v7 = a.T
//
// Warp-aligned classes + vectorized loads:
//   warp 0: x3,x4  — dot2 via 2x LDG.64 (float2 row fetch)
//   warp 1: v4,v6  — dot2 via 2x LDG.64
//   warp 2: copies (scalar LDG) + dot4 via 4x LDG.128 + register selects
//
// Problem is launch-overhead-bound (~3.7-4.0us kernel / ~4.83-4.86us wall
// floor measured across four bodies). This round minimizes LDG queue
// entries on the critical path; expected delta is at/below one timer tick.

__global__ void __launch_bounds__(96, 1)
model_kernel(const float* __restrict__ x1,
             const float* __restrict__ x2,
             float* __restrict__ out) {
    const int t = threadIdx.x;   // blockDim.x == 96 exactly

    if (t < 64) {
        // ---- dot2 warps: r = dot(a_row[ia], q_row[ib]) with 2-elem rows
        const int u = t & 31;
        const int v = u & 15;
        int ia, ib, pos;
        const float2* q2;
        if (t < 32) {                       // warp 0: x3 (u<16), x4 (u>=16)
            const bool swap = u >= 16;      // x4[i][j] = x3[j][i]
            ia = swap ? (v & 3) : (v >> 2);
            ib = swap ? (v >> 2) : (v & 3);
            q2 = (const float2*)x2;
            pos = t;                        // out 0..31
        } else {                            // warp 1: v4 (u<16), v6 (u>=16)
            ia = v >> 2;
            ib = v & 3;
            const bool is_v4 = u < 16;
            q2 = (const float2*)(is_v4 ? x1 : x2);
            pos = is_v4 ? (52 + v) : (72 + v);
        }
        const float2 ar = ((const float2*)x1)[ia];
        const float2 qr = q2[ib];
        out[pos] = ar.x * qr.x + ar.y * qr.y;
    } else {
        // ---- warp 2: copies (u<24) + dot4 (u>=24)
        const int u = t - 64;
        if (u < 24) {
            const int v = (u - 8) & 7;      // local idx for v2/v7
            const bool ident = u < 8;       // v1 = x1 flat
            const int idx = ident ? u : ((v & 3) * 2 + (v >> 2));
            const int pos = ident ? (32 + u) : ((u < 16) ? (40 + v) : (88 + v));
            out[pos] = x1[idx];
        } else {
            const int v = u - 24;           // 0..3 -> v3, 4..7 -> v5
            const int w = v & 3;
            const int i = w >> 1, j = w & 1;
            const bool is_v3 = v < 4;
            const float* p = is_v3 ? x1 : x2;   // v3: a.T@a, v5: b.T@a
            const int pos = is_v3 ? (48 + w) : (68 + w);

            // Fetch both 8-float operands as 2x float4 each, select in regs.
            const float4 a0 = ((const float4*)x1)[0];   // x1[0..3]
            const float4 a1 = ((const float4*)x1)[1];   // x1[4..7]
            const float4 p0 = ((const float4*)p)[0];    // p[0..3]
            const float4 p1 = ((const float4*)p)[1];    // p[4..7]

            // column j of a (stride 2): {a0.x/a0.y, a0.z/a0.w, a1.x/a1.y, a1.z/a1.w}
            const float aj0 = j ? a0.y : a0.x;
            const float aj1 = j ? a0.w : a0.z;
            const float aj2 = j ? a1.y : a1.x;
            const float aj3 = j ? a1.w : a1.z;
            // column i of p
            const float pi0 = i ? p0.y : p0.x;
            const float pi1 = i ? p0.w : p0.z;
            const float pi2 = i ? p1.y : p1.x;
            const float pi3 = i ? p1.w : p1.z;

            out[pos] = pi0 * aj0 + pi1 * aj1 + pi2 * aj2 + pi3 * aj3;
        }
    }
}

extern "C" void kernel_launch(void* const* d_in, const int* in_sizes, int n_in,
                              void* d_out, int out_size) {
    const float* x1 = (const float*)d_in[0];
    const float* x2 = (const float*)d_in[1];
    float* out = (float*)d_out;
    model_kernel<<<1, 96>>>(x1, x2, out);
}

// round 6
// speedup vs baseline: 1.2083x; 1.2083x over previous
#include <cuda_runtime.h>

// 96 fp32 outputs, a = x1.reshape(4,2), b = x2.reshape(4,2):
//   [ 0,16) x3 = a@b.T   [16,32) x4 = x3.T   [32,40) v1 = a
//   [40,48) v2 = a.T     [48,52) v3 = a.T@a  [52,68) v4 = a@a.T
//   [68,72) v5 = b.T@a   [72,88) v6 = x3     [88,96) v7 = a.T
//
// Warp-aligned classes + vectorized loads:
//   warp 0: x3,x4  — dot2 via 2x LDG.64 (float2 row fetch)
//   warp 1: v4,v6  — dot2 via 2x LDG.64
//   warp 2: copies (scalar LDG) + dot4 via 4x LDG.128 + register selects
//
// R5 re-bench: this body measured the LOWEST ncu kernel dur (3.584us) but
// drew a high wall sample (5.57us vs the 4.83-4.86 floor). Identical
// resubmission to discriminate wall-timer noise from a real regression.

__global__ void __launch_bounds__(96, 1)
model_kernel(const float* __restrict__ x1,
             const float* __restrict__ x2,
             float* __restrict__ out) {
    const int t = threadIdx.x;   // blockDim.x == 96 exactly

    if (t < 64) {
        // ---- dot2 warps: r = dot(a_row[ia], q_row[ib]) with 2-elem rows
        const int u = t & 31;
        const int v = u & 15;
        int ia, ib, pos;
        const float2* q2;
        if (t < 32) {                       // warp 0: x3 (u<16), x4 (u>=16)
            const bool swap = u >= 16;      // x4[i][j] = x3[j][i]
            ia = swap ? (v & 3) : (v >> 2);
            ib = swap ? (v >> 2) : (v & 3);
            q2 = (const float2*)x2;
            pos = t;                        // out 0..31
        } else {                            // warp 1: v4 (u<16), v6 (u>=16)
            ia = v >> 2;
            ib = v & 3;
            const bool is_v4 = u < 16;
            q2 = (const float2*)(is_v4 ? x1 : x2);
            pos = is_v4 ? (52 + v) : (72 + v);
        }
        const float2 ar = ((const float2*)x1)[ia];
        const float2 qr = q2[ib];
        out[pos] = ar.x * qr.x + ar.y * qr.y;
    } else {
        // ---- warp 2: copies (u<24) + dot4 (u>=24)
        const int u = t - 64;
        if (u < 24) {
            const int v = (u - 8) & 7;      // local idx for v2/v7
            const bool ident = u < 8;       // v1 = x1 flat
            const int idx = ident ? u : ((v & 3) * 2 + (v >> 2));
            const int pos = ident ? (32 + u) : ((u < 16) ? (40 + v) : (88 + v));
            out[pos] = x1[idx];
        } else {
            const int v = u - 24;           // 0..3 -> v3, 4..7 -> v5
            const int w = v & 3;
            const int i = w >> 1, j = w & 1;
            const bool is_v3 = v < 4;
            const float* p = is_v3 ? x1 : x2;   // v3: a.T@a, v5: b.T@a
            const int pos = is_v3 ? (48 + w) : (68 + w);

            // Fetch both 8-float operands as 2x float4 each, select in regs.
            const float4 a0 = ((const float4*)x1)[0];   // x1[0..3]
            const float4 a1 = ((const float4*)x1)[1];   // x1[4..7]
            const float4 p0 = ((const float4*)p)[0];    // p[0..3]
            const float4 p1 = ((const float4*)p)[1];    // p[4..7]

            // column j of a (stride 2): {a0.x/a0.y, a0.z/a0.w, a1.x/a1.y, a1.z/a1.w}
            const float aj0 = j ? a0.y : a0.x;
            const float aj1 = j ? a0.w : a0.z;
            const float aj2 = j ? a1.y : a1.x;
            const float aj3 = j ? a1.w : a1.z;
            // column i of p
            const float pi0 = i ? p0.y : p0.x;
            const float pi1 = i ? p0.w : p0.z;
            const float pi2 = i ? p1.y : p1.x;
            const float pi3 = i ? p1.w : p1.z;

            out[pos] = pi0 * aj0 + pi1 * aj1 + pi2 * aj2 + pi3 * aj3;
        }
    }
}

extern "C" void kernel_launch(void* const* d_in, const int* in_sizes, int n_in,
                              void* d_out, int out_size) {
    const float* x1 = (const float*)d_in[0];
    const float* x2 = (const float*)d_in[1];
    float* out = (float*)d_out;
    model_kernel<<<1, 96>>>(x1, x2, out);
}

// round 7
// speedup vs baseline: 1.2168x; 1.0070x over previous
#include <cuda_runtime.h>

// 96 fp32 outputs, a = x1.reshape(4,2), b = x2.reshape(4,2):
//   [ 0,16) x3 = a@b.T   [16,32) x4 = x3.T   [32,40) v1 = a
//   [40,48) v2 = a.T     [48,52) v3 = a.T@a  [52,68) v4 = a@a.T
//   [68,72) v5 = b.T@a   [72,88) v6 = x3     [88,96) v7 = a.T
//
// Warp-aligned classes + vectorized loads:
//   warp 0: x3,x4  — dot2 via 2x LDG.64 (float2 row fetch)
//   warp 1: v4,v6  — dot2 via 2x LDG.64
//   warp 2: copies (scalar LDG) + dot4 via 4x LDG.128 + register selects
//
// Wall samples for this exact body: {5.568, 4.608} us; scalar bodies:
// {4.832-4.864}. ncu kernel dur: {3.584, 3.680} vs scalar {3.74-4.06}.
// Third identical sample to confirm the 4.608 before committing as final.

__global__ void __launch_bounds__(96, 1)
model_kernel(const float* __restrict__ x1,
             const float* __restrict__ x2,
             float* __restrict__ out) {
    const int t = threadIdx.x;   // blockDim.x == 96 exactly

    if (t < 64) {
        // ---- dot2 warps: r = dot(a_row[ia], q_row[ib]) with 2-elem rows
        const int u = t & 31;
        const int v = u & 15;
        int ia, ib, pos;
        const float2* q2;
        if (t < 32) {                       // warp 0: x3 (u<16), x4 (u>=16)
            const bool swap = u >= 16;      // x4[i][j] = x3[j][i]
            ia = swap ? (v & 3) : (v >> 2);
            ib = swap ? (v >> 2) : (v & 3);
            q2 = (const float2*)x2;
            pos = t;                        // out 0..31
        } else {                            // warp 1: v4 (u<16), v6 (u>=16)
            ia = v >> 2;
            ib = v & 3;
            const bool is_v4 = u < 16;
            q2 = (const float2*)(is_v4 ? x1 : x2);
            pos = is_v4 ? (52 + v) : (72 + v);
        }
        const float2 ar = ((const float2*)x1)[ia];
        const float2 qr = q2[ib];
        out[pos] = ar.x * qr.x + ar.y * qr.y;
    } else {
        // ---- warp 2: copies (u<24) + dot4 (u>=24)
        const int u = t - 64;
        if (u < 24) {
            const int v = (u - 8) & 7;      // local idx for v2/v7
            const bool ident = u < 8;       // v1 = x1 flat
            const int idx = ident ? u : ((v & 3) * 2 + (v >> 2));
            const int pos = ident ? (32 + u) : ((u < 16) ? (40 + v) : (88 + v));
            out[pos] = x1[idx];
        } else {
            const int v = u - 24;           // 0..3 -> v3, 4..7 -> v5
            const int w = v & 3;
            const int i = w >> 1, j = w & 1;
            const bool is_v3 = v < 4;
            const float* p = is_v3 ? x1 : x2;   // v3: a.T@a, v5: b.T@a
            const int pos = is_v3 ? (48 + w) : (68 + w);

            // Fetch both 8-float operands as 2x float4 each, select in regs.
            const float4 a0 = ((const float4*)x1)[0];   // x1[0..3]
            const float4 a1 = ((const float4*)x1)[1];   // x1[4..7]
            const float4 p0 = ((const float4*)p)[0];    // p[0..3]
            const float4 p1 = ((const float4*)p)[1];    // p[4..7]

            // column j of a (stride 2): {a0.x/a0.y, a0.z/a0.w, a1.x/a1.y, a1.z/a1.w}
            const float aj0 = j ? a0.y : a0.x;
            const float aj1 = j ? a0.w : a0.z;
            const float aj2 = j ? a1.y : a1.x;
            const float aj3 = j ? a1.w : a1.z;
            // column i of p
            const float pi0 = i ? p0.y : p0.x;
            const float pi1 = i ? p0.w : p0.z;
            const float pi2 = i ? p1.y : p1.x;
            const float pi3 = i ? p1.w : p1.z;

            out[pos] = pi0 * aj0 + pi1 * aj1 + pi2 * aj2 + pi3 * aj3;
        }
    }
}

extern "C" void kernel_launch(void* const* d_in, const int* in_sizes, int n_in,
                              void* d_out, int out_size) {
    const float* x1 = (const float*)d_in[0];
    const float* x2 = (const float*)d_in[1];
    float* out = (float*)d_out;
    model_kernel<<<1, 96>>>(x1, x2, out);
}